// round 4
// baseline (speedup 1.0000x reference)
#include <cuda_runtime.h>

#define THREADS 1024
#define VPT4    8          // float4 per thread: 8*1024 = 8192 >= 8000
#define N_COLS  32000
#define N4      8000       // 32000 / 4, exact
#define N_ITER  50

__device__ __forceinline__ float warp_sum(float v) {
    #pragma unroll
    for (int o = 16; o > 0; o >>= 1) v += __shfl_xor_sync(0xffffffffu, v, o);
    return v;
}
__device__ __forceinline__ float warp_max(float v) {
    #pragma unroll
    for (int o = 16; o > 0; o >>= 1) v = fmaxf(v, __shfl_xor_sync(0xffffffffu, v, o));
    return v;
}
__device__ __forceinline__ float warp_min(float v) {
    #pragma unroll
    for (int o = 16; o > 0; o >>= 1) v = fminf(v, __shfl_xor_sync(0xffffffffu, v, o));
    return v;
}

__global__ void __launch_bounds__(THREADS, 1)
entmax_kernel(const float* __restrict__ x, float* __restrict__ out) {
    __shared__ float s_a[32];
    __shared__ float s_b[32];
    __shared__ float s_bcast0;
    __shared__ float s_bcast1;

    const int row = blockIdx.x;
    const int tid = threadIdx.x;
    const int wid = tid >> 5;
    const int lid = tid & 31;

    const float4* __restrict__ xrow =
        reinterpret_cast<const float4*>(x + (size_t)row * N_COLS);
    float4* __restrict__ orow =
        reinterpret_cast<float4*>(out + (size_t)row * N_COLS);

    float4 v[VPT4];

    // ---- load row (coalesced float4), fused local min/max ----
    float lmax = __int_as_float(0xff800000);  // -inf
    float lmin = __int_as_float(0x7f800000);  // +inf
    #pragma unroll
    for (int i = 0; i < VPT4; i++) {
        const int idx = i * THREADS + tid;
        if (idx < N4) {
            v[i] = xrow[idx];
            lmax = fmaxf(lmax, fmaxf(fmaxf(v[i].x, v[i].y), fmaxf(v[i].z, v[i].w)));
            lmin = fminf(lmin, fminf(fminf(v[i].x, v[i].y), fminf(v[i].z, v[i].w)));
        } else {
            // padding: acts as a very negative logit -> contributes 0 everywhere
            v[i] = make_float4(-1e30f, -1e30f, -1e30f, -1e30f);
        }
    }

    // ---- fused block reduce (max & min) ----
    lmax = warp_max(lmax);
    lmin = warp_min(lmin);
    if (lid == 0) { s_a[wid] = lmax; s_b[wid] = lmin; }
    __syncthreads();
    if (wid == 0) {
        float m = s_a[lid];
        float n = s_b[lid];
        m = warp_max(m);
        n = warp_min(n);
        if (lid == 0) { s_bcast0 = m; s_bcast1 = n; }
    }
    __syncthreads();
    const float maxv = s_bcast0;
    const float minv = s_bcast1;

    // ---- scalar fp32 replica of the reference recurrence under the
    //      invariant constraint(tau_k) > 0 for all k (tmax <- tau each step,
    //      tmin fixed). Invariant is GUARANTEED when tau_1^2 > 1:
    //      f(tau) = sum clip(z-tau)^2 >= clip(0-tau)^2 = tau^2 (max elem has
    //      z = 0), all iterates tau_k <= tau_1, f decreasing. ----
    const float m_shift = minv - maxv;
    const float tmin0 = m_shift - 1.0f;
    float tmaxr = 0.0f;
    #pragma unroll
    for (int it = 0; it < N_ITER; it++) {
        tmaxr = 0.5f * (tmin0 + tmaxr);
    }
    const float tau_fast = 0.5f * (tmin0 + tmaxr);
    const bool fast = (m_shift <= -1.02f);   // tau_1 = 0.5*(m_shift-1) <= -1.01

    float tau, total;

    if (fast) {
        // ---- single sum pass at tau_fast (z computed inline) ----
        float s = 0.0f;
        #pragma unroll
        for (int i = 0; i < VPT4; i++) {
            float d;
            d = fmaxf(0.5f * (v[i].x - maxv) - tau_fast, 0.0f); s = fmaf(d, d, s);
            d = fmaxf(0.5f * (v[i].y - maxv) - tau_fast, 0.0f); s = fmaf(d, d, s);
            d = fmaxf(0.5f * (v[i].z - maxv) - tau_fast, 0.0f); s = fmaf(d, d, s);
            d = fmaxf(0.5f * (v[i].w - maxv) - tau_fast, 0.0f); s = fmaf(d, d, s);
        }
        s = warp_sum(s);
        if (lid == 0) s_a[wid] = s;
        __syncthreads();
        if (wid == 0) {
            float t = s_a[lid];
            t = warp_sum(t);
            if (lid == 0) s_bcast0 = t;
        }
        __syncthreads();
        tau = tau_fast;
        total = s_bcast0;
    } else {
        // ---- fallback: exact reference-semantics bisection over registers.
        //      (Never taken for this data; guards pathological inputs.) ----
        float tmin = tmin0, tmax = 0.0f;
        for (int it = 0; it < N_ITER; it++) {
            const float t = 0.5f * (tmin + tmax);
            float s = 0.0f;
            #pragma unroll
            for (int i = 0; i < VPT4; i++) {
                float d;
                d = fmaxf(0.5f * (v[i].x - maxv) - t, 0.0f); s = fmaf(d, d, s);
                d = fmaxf(0.5f * (v[i].y - maxv) - t, 0.0f); s = fmaf(d, d, s);
                d = fmaxf(0.5f * (v[i].z - maxv) - t, 0.0f); s = fmaf(d, d, s);
                d = fmaxf(0.5f * (v[i].w - maxv) - t, 0.0f); s = fmaf(d, d, s);
            }
            s = warp_sum(s);
            if (lid == 0) s_a[wid] = s;
            __syncthreads();
            if (wid == 0) {
                float u = s_a[lid];
                u = warp_sum(u);
                if (lid == 0) s_bcast0 = u;
            }
            __syncthreads();
            const float constraint = s_bcast0 - 1.0f;
            if (constraint < 0.0f) tmin = t;
            if (constraint > 0.0f) tmax = t;
        }
        tau = 0.5f * (tmin + tmax);
        float s = 0.0f;
        #pragma unroll
        for (int i = 0; i < VPT4; i++) {
            float d;
            d = fmaxf(0.5f * (v[i].x - maxv) - tau, 0.0f); s = fmaf(d, d, s);
            d = fmaxf(0.5f * (v[i].y - maxv) - tau, 0.0f); s = fmaf(d, d, s);
            d = fmaxf(0.5f * (v[i].z - maxv) - tau, 0.0f); s = fmaf(d, d, s);
            d = fmaxf(0.5f * (v[i].w - maxv) - tau, 0.0f); s = fmaf(d, d, s);
        }
        s = warp_sum(s);
        if (lid == 0) s_a[wid] = s;
        __syncthreads();
        if (wid == 0) {
            float u = s_a[lid];
            u = warp_sum(u);
            if (lid == 0) s_bcast0 = u;
        }
        __syncthreads();
        total = s_bcast0;
    }

    const float inv = 1.0f / (total + 1e-12f);

    // ---- write y = clip(0.5*(x-max) - tau)^2 * inv ----
    #pragma unroll
    for (int i = 0; i < VPT4; i++) {
        const int idx = i * THREADS + tid;
        if (idx < N4) {
            float4 o;
            float d;
            d = fmaxf(0.5f * (v[i].x - maxv) - tau, 0.0f); o.x = d * d * inv;
            d = fmaxf(0.5f * (v[i].y - maxv) - tau, 0.0f); o.y = d * d * inv;
            d = fmaxf(0.5f * (v[i].z - maxv) - tau, 0.0f); o.z = d * d * inv;
            d = fmaxf(0.5f * (v[i].w - maxv) - tau, 0.0f); o.w = d * d * inv;
            orow[idx] = o;
        }
    }
}

extern "C" void kernel_launch(void* const* d_in, const int* in_sizes, int n_in,
                              void* d_out, int out_size) {
    const float* x = (const float*)d_in[0];
    float* out = (float*)d_out;
    const int rows = in_sizes[0] / N_COLS;   // 4096
    entmax_kernel<<<rows, THREADS>>>(x, out);
}

// round 5
// speedup vs baseline: 1.0224x; 1.0224x over previous
#include <cuda_runtime.h>

#define THREADS 1024
#define VPT4    8          // float4 per thread: 8*1024 = 8192 >= 8000
#define N_COLS  32000
#define N4      8000       // 32000 / 4, exact
#define N_ITER  50

__device__ __forceinline__ float warp_sum(float v) {
    #pragma unroll
    for (int o = 16; o > 0; o >>= 1) v += __shfl_xor_sync(0xffffffffu, v, o);
    return v;
}
__device__ __forceinline__ float warp_max(float v) {
    #pragma unroll
    for (int o = 16; o > 0; o >>= 1) v = fmaxf(v, __shfl_xor_sync(0xffffffffu, v, o));
    return v;
}
__device__ __forceinline__ float warp_min(float v) {
    #pragma unroll
    for (int o = 16; o > 0; o >>= 1) v = fminf(v, __shfl_xor_sync(0xffffffffu, v, o));
    return v;
}

__global__ void __launch_bounds__(THREADS, 1)
entmax_kernel(const float* __restrict__ x, float* __restrict__ out) {
    __shared__ float s_a[32];
    __shared__ float s_b[32];
    __shared__ float s_bcast0;
    __shared__ float s_bcast1;

    const int row = blockIdx.x;
    const int tid = threadIdx.x;
    const int wid = tid >> 5;
    const int lid = tid & 31;

    const float4* __restrict__ xrow =
        reinterpret_cast<const float4*>(x + (size_t)row * N_COLS);
    float4* __restrict__ orow =
        reinterpret_cast<float4*>(out + (size_t)row * N_COLS);

    const float NEG_BIG = -1e30f;
    float4 v[VPT4];

    // ---- load row (coalesced float4), track local min/max ----
    float lmax = __int_as_float(0xff800000);  // -inf
    float lmin = __int_as_float(0x7f800000);  // +inf
    #pragma unroll
    for (int i = 0; i < VPT4; i++) {
        const int idx = i * THREADS + tid;
        if (idx < N4) {
            v[i] = xrow[idx];
            lmax = fmaxf(lmax, fmaxf(fmaxf(v[i].x, v[i].y), fmaxf(v[i].z, v[i].w)));
            lmin = fminf(lmin, fminf(fminf(v[i].x, v[i].y), fminf(v[i].z, v[i].w)));
        } else {
            v[i] = make_float4(NEG_BIG, NEG_BIG, NEG_BIG, NEG_BIG);
        }
    }

    // ---- fused block reduce (max & min) ----
    lmax = warp_max(lmax);
    lmin = warp_min(lmin);
    if (lid == 0) { s_a[wid] = lmax; s_b[wid] = lmin; }
    __syncthreads();
    if (wid == 0) {
        float m = s_a[lid];
        float n = s_b[lid];
        m = warp_max(m);
        n = warp_min(n);
        if (lid == 0) { s_bcast0 = m; s_bcast1 = n; }
    }
    __syncthreads();
    const float maxv = s_bcast0;
    const float minv = s_bcast1;

    // ---- z = 0.5 * (x - max); padding lanes stay ~-1e30 (clip -> 0) ----
    #pragma unroll
    for (int i = 0; i < VPT4; i++) {
        const int idx = i * THREADS + tid;
        if (idx < N4) {
            v[i].x = 0.5f * (v[i].x - maxv);
            v[i].y = 0.5f * (v[i].y - maxv);
            v[i].z = 0.5f * (v[i].z - maxv);
            v[i].w = 0.5f * (v[i].w - maxv);
        }
    }

    // ---- scalar fp32 replica of the reference recurrence under the
    //      invariant constraint(tau_k) > 0 for all k (tmax <- tau each step,
    //      tmin fixed). Invariant is ANALYTICALLY GUARANTEED when
    //      tau_1^2 > 1:  f(tau) = sum clip(z-tau)^2 >= clip(0-tau)^2 = tau^2
    //      (the max element has z = 0), f is decreasing, and all iterates
    //      tau_k <= tau_1. So m_shift <= -1.02 => f(tau_k) >= 1.0201 > 1. ----
    const float m_shift = minv - maxv;
    const float tmin0 = m_shift - 1.0f;
    float tmaxr = 0.0f;
    #pragma unroll
    for (int it = 0; it < N_ITER; it++) {
        tmaxr = 0.5f * (tmin0 + tmaxr);
    }
    const float tau_fast = 0.5f * (tmin0 + tmaxr);
    const bool fast = (m_shift <= -1.02f);

    float tau, total;

    if (fast) {
        // ---- single sum pass at tau_fast over shifted registers ----
        float s = 0.0f;
        #pragma unroll
        for (int i = 0; i < VPT4; i++) {
            float d;
            d = fmaxf(v[i].x - tau_fast, 0.0f); s = fmaf(d, d, s);
            d = fmaxf(v[i].y - tau_fast, 0.0f); s = fmaf(d, d, s);
            d = fmaxf(v[i].z - tau_fast, 0.0f); s = fmaf(d, d, s);
            d = fmaxf(v[i].w - tau_fast, 0.0f); s = fmaf(d, d, s);
        }
        s = warp_sum(s);
        if (lid == 0) s_a[wid] = s;
        __syncthreads();
        if (wid == 0) {
            float t = s_a[lid];
            t = warp_sum(t);
            if (lid == 0) s_bcast0 = t;
        }
        __syncthreads();
        tau = tau_fast;
        total = s_bcast0;
    } else {
        // ---- fallback: exact reference-semantics bisection over registers.
        //      (Never taken for this data; guards pathological inputs.) ----
        float tmin = tmin0, tmax = 0.0f;
        for (int it = 0; it < N_ITER; it++) {
            const float t = 0.5f * (tmin + tmax);
            float s = 0.0f;
            #pragma unroll
            for (int i = 0; i < VPT4; i++) {
                float d;
                d = fmaxf(v[i].x - t, 0.0f); s = fmaf(d, d, s);
                d = fmaxf(v[i].y - t, 0.0f); s = fmaf(d, d, s);
                d = fmaxf(v[i].z - t, 0.0f); s = fmaf(d, d, s);
                d = fmaxf(v[i].w - t, 0.0f); s = fmaf(d, d, s);
            }
            s = warp_sum(s);
            if (lid == 0) s_a[wid] = s;
            __syncthreads();
            if (wid == 0) {
                float u = s_a[lid];
                u = warp_sum(u);
                if (lid == 0) s_bcast0 = u;
            }
            __syncthreads();
            const float constraint = s_bcast0 - 1.0f;
            if (constraint < 0.0f) tmin = t;
            if (constraint > 0.0f) tmax = t;
        }
        tau = 0.5f * (tmin + tmax);
        float s = 0.0f;
        #pragma unroll
        for (int i = 0; i < VPT4; i++) {
            float d;
            d = fmaxf(v[i].x - tau, 0.0f); s = fmaf(d, d, s);
            d = fmaxf(v[i].y - tau, 0.0f); s = fmaf(d, d, s);
            d = fmaxf(v[i].z - tau, 0.0f); s = fmaf(d, d, s);
            d = fmaxf(v[i].w - tau, 0.0f); s = fmaf(d, d, s);
        }
        s = warp_sum(s);
        if (lid == 0) s_a[wid] = s;
        __syncthreads();
        if (wid == 0) {
            float u = s_a[lid];
            u = warp_sum(u);
            if (lid == 0) s_bcast0 = u;
        }
        __syncthreads();
        total = s_bcast0;
    }

    const float inv = 1.0f / (total + 1e-12f);

    // ---- write y = clip(z - tau)^2 * inv ----
    #pragma unroll
    for (int i = 0; i < VPT4; i++) {
        const int idx = i * THREADS + tid;
        if (idx < N4) {
            float4 o;
            float d;
            d = fmaxf(v[i].x - tau, 0.0f); o.x = d * d * inv;
            d = fmaxf(v[i].y - tau, 0.0f); o.y = d * d * inv;
            d = fmaxf(v[i].z - tau, 0.0f); o.z = d * d * inv;
            d = fmaxf(v[i].w - tau, 0.0f); o.w = d * d * inv;
            orow[idx] = o;
        }
    }
}

extern "C" void kernel_launch(void* const* d_in, const int* in_sizes, int n_in,
                              void* d_out, int out_size) {
    const float* x = (const float*)d_in[0];
    float* out = (float*)d_out;
    const int rows = in_sizes[0] / N_COLS;   // 4096
    entmax_kernel<<<rows, THREADS>>>(x, out);
}

// round 6
// speedup vs baseline: 1.4742x; 1.4420x over previous
#include <cuda_runtime.h>

#define NT      512
#define RV4     7                 // float4 per thread in registers
#define SJ      9                 // smem float4 iterations per thread
#define N_COLS  32000
#define N4      8000              // float4 per row
#define R4MAX   (RV4 * NT)        // 3584 float4 held in registers
#define SMEM4   (N4 - R4MAX)      // 4416 float4 held in smem
#define SMEM_BYTES (SMEM4 * 16)   // 70656
#define N_ITER  50

__device__ __forceinline__ float warp_sum(float v) {
    #pragma unroll
    for (int o = 16; o > 0; o >>= 1) v += __shfl_xor_sync(0xffffffffu, v, o);
    return v;
}
__device__ __forceinline__ float warp_max(float v) {
    #pragma unroll
    for (int o = 16; o > 0; o >>= 1) v = fmaxf(v, __shfl_xor_sync(0xffffffffu, v, o));
    return v;
}
__device__ __forceinline__ float warp_min(float v) {
    #pragma unroll
    for (int o = 16; o > 0; o >>= 1) v = fminf(v, __shfl_xor_sync(0xffffffffu, v, o));
    return v;
}

__global__ void __launch_bounds__(NT, 2)
entmax_kernel(const float* __restrict__ x, float* __restrict__ out) {
    extern __shared__ float4 sdat[];          // SMEM4 float4, thread-private slots
    __shared__ float s_a[16];
    __shared__ float s_b[16];
    __shared__ float s_bc0;
    __shared__ float s_bc1;

    const int row = blockIdx.x;
    const int tid = threadIdx.x;
    const int wid = tid >> 5;                 // 0..15
    const int lid = tid & 31;

    const float4* __restrict__ xrow =
        reinterpret_cast<const float4*>(x + (size_t)row * N_COLS);
    float4* __restrict__ orow =
        reinterpret_cast<float4*>(out + (size_t)row * N_COLS);

    float4 v[RV4];

    // ---- load: reg part + smem part, fused local min/max ----
    float lmax = __int_as_float(0xff800000);  // -inf
    float lmin = __int_as_float(0x7f800000);  // +inf
    #pragma unroll
    for (int i = 0; i < RV4; i++) {
        v[i] = xrow[i * NT + tid];
        lmax = fmaxf(lmax, fmaxf(fmaxf(v[i].x, v[i].y), fmaxf(v[i].z, v[i].w)));
        lmin = fminf(lmin, fminf(fminf(v[i].x, v[i].y), fminf(v[i].z, v[i].w)));
    }
    #pragma unroll
    for (int j = 0; j < SJ; j++) {
        const int idx = R4MAX + j * NT + tid;
        if (idx < N4) {
            float4 a = xrow[idx];
            sdat[idx - R4MAX] = a;
            lmax = fmaxf(lmax, fmaxf(fmaxf(a.x, a.y), fmaxf(a.z, a.w)));
            lmin = fminf(lmin, fminf(fminf(a.x, a.y), fminf(a.z, a.w)));
        }
    }

    // ---- block reduce max & min (16 warps) ----
    lmax = warp_max(lmax);
    lmin = warp_min(lmin);
    if (lid == 0) { s_a[wid] = lmax; s_b[wid] = lmin; }
    __syncthreads();
    if (wid == 0) {
        float m = (lid < 16) ? s_a[lid] : -3.4e38f;
        float n = (lid < 16) ? s_b[lid] :  3.4e38f;
        m = warp_max(m);
        n = warp_min(n);
        if (lid == 0) { s_bc0 = m; s_bc1 = n; }
    }
    __syncthreads();
    const float maxv = s_bc0;
    const float minv = s_bc1;

    // ---- shift register part in place: z = 0.5 * (x - max) ----
    #pragma unroll
    for (int i = 0; i < RV4; i++) {
        v[i].x = 0.5f * (v[i].x - maxv);
        v[i].y = 0.5f * (v[i].y - maxv);
        v[i].z = 0.5f * (v[i].z - maxv);
        v[i].w = 0.5f * (v[i].w - maxv);
    }

    // ---- scalar fp32 replica of reference recurrence under constraint>0
    //      invariant (tmax <- tau each iter, tmin fixed). Analytically valid
    //      when tau_1^2 > 1: f(tau) >= clip(0-tau)^2 = tau^2 (max elem has
    //      z=0), f decreasing, all iterates <= tau_1. ----
    const float m_shift = minv - maxv;
    const float tmin0 = m_shift - 1.0f;
    float tmaxr = 0.0f;
    #pragma unroll
    for (int it = 0; it < N_ITER; it++) tmaxr = 0.5f * (tmin0 + tmaxr);
    const float tau_fast = 0.5f * (tmin0 + tmaxr);
    const bool fast = (m_shift <= -1.02f);

    // ---- unconditional sum pass at tau_fast (R3-proven structure) ----
    float s = 0.0f;
    #pragma unroll
    for (int i = 0; i < RV4; i++) {
        float d;
        d = fmaxf(v[i].x - tau_fast, 0.0f); s = fmaf(d, d, s);
        d = fmaxf(v[i].y - tau_fast, 0.0f); s = fmaf(d, d, s);
        d = fmaxf(v[i].z - tau_fast, 0.0f); s = fmaf(d, d, s);
        d = fmaxf(v[i].w - tau_fast, 0.0f); s = fmaf(d, d, s);
    }
    #pragma unroll
    for (int j = 0; j < SJ; j++) {
        const int idx = R4MAX + j * NT + tid;
        if (idx < N4) {
            float4 a = sdat[idx - R4MAX];
            float d;
            d = fmaxf(0.5f * (a.x - maxv) - tau_fast, 0.0f); s = fmaf(d, d, s);
            d = fmaxf(0.5f * (a.y - maxv) - tau_fast, 0.0f); s = fmaf(d, d, s);
            d = fmaxf(0.5f * (a.z - maxv) - tau_fast, 0.0f); s = fmaf(d, d, s);
            d = fmaxf(0.5f * (a.w - maxv) - tau_fast, 0.0f); s = fmaf(d, d, s);
        }
    }
    s = warp_sum(s);
    if (lid == 0) s_a[wid] = s;
    __syncthreads();
    if (wid == 0) {
        float t = (lid < 16) ? s_a[lid] : 0.0f;
        t = warp_sum(t);
        if (lid == 0) s_bc0 = t;
    }
    __syncthreads();

    float tau = tau_fast;
    float total = s_bc0;

    if (!fast) {
        // ---- fallback: exact reference-semantics bisection (regs + smem).
        //      Never taken for this data; guards pathological inputs. ----
        float tmin = tmin0, tmax = 0.0f;
        for (int it = 0; it < N_ITER; it++) {
            const float t = 0.5f * (tmin + tmax);
            float ss = 0.0f;
            #pragma unroll
            for (int i = 0; i < RV4; i++) {
                float d;
                d = fmaxf(v[i].x - t, 0.0f); ss = fmaf(d, d, ss);
                d = fmaxf(v[i].y - t, 0.0f); ss = fmaf(d, d, ss);
                d = fmaxf(v[i].z - t, 0.0f); ss = fmaf(d, d, ss);
                d = fmaxf(v[i].w - t, 0.0f); ss = fmaf(d, d, ss);
            }
            #pragma unroll
            for (int j = 0; j < SJ; j++) {
                const int idx = R4MAX + j * NT + tid;
                if (idx < N4) {
                    float4 a = sdat[idx - R4MAX];
                    float d;
                    d = fmaxf(0.5f * (a.x - maxv) - t, 0.0f); ss = fmaf(d, d, ss);
                    d = fmaxf(0.5f * (a.y - maxv) - t, 0.0f); ss = fmaf(d, d, ss);
                    d = fmaxf(0.5f * (a.z - maxv) - t, 0.0f); ss = fmaf(d, d, ss);
                    d = fmaxf(0.5f * (a.w - maxv) - t, 0.0f); ss = fmaf(d, d, ss);
                }
            }
            ss = warp_sum(ss);
            if (lid == 0) s_a[wid] = ss;
            __syncthreads();
            if (wid == 0) {
                float u = (lid < 16) ? s_a[lid] : 0.0f;
                u = warp_sum(u);
                if (lid == 0) s_bc0 = u;
            }
            __syncthreads();
            const float constraint = s_bc0 - 1.0f;
            if (constraint < 0.0f) tmin = t;
            if (constraint > 0.0f) tmax = t;
        }
        tau = 0.5f * (tmin + tmax);
        float ss = 0.0f;
        #pragma unroll
        for (int i = 0; i < RV4; i++) {
            float d;
            d = fmaxf(v[i].x - tau, 0.0f); ss = fmaf(d, d, ss);
            d = fmaxf(v[i].y - tau, 0.0f); ss = fmaf(d, d, ss);
            d = fmaxf(v[i].z - tau, 0.0f); ss = fmaf(d, d, ss);
            d = fmaxf(v[i].w - tau, 0.0f); ss = fmaf(d, d, ss);
        }
        #pragma unroll
        for (int j = 0; j < SJ; j++) {
            const int idx = R4MAX + j * NT + tid;
            if (idx < N4) {
                float4 a = sdat[idx - R4MAX];
                float d;
                d = fmaxf(0.5f * (a.x - maxv) - tau, 0.0f); ss = fmaf(d, d, ss);
                d = fmaxf(0.5f * (a.y - maxv) - tau, 0.0f); ss = fmaf(d, d, ss);
                d = fmaxf(0.5f * (a.z - maxv) - tau, 0.0f); ss = fmaf(d, d, ss);
                d = fmaxf(0.5f * (a.w - maxv) - tau, 0.0f); ss = fmaf(d, d, ss);
            }
        }
        ss = warp_sum(ss);
        if (lid == 0) s_a[wid] = ss;
        __syncthreads();
        if (wid == 0) {
            float u = (lid < 16) ? s_a[lid] : 0.0f;
            u = warp_sum(u);
            if (lid == 0) s_bc0 = u;
        }
        __syncthreads();
        total = s_bc0;
    }

    const float inv = 1.0f / (total + 1e-12f);

    // ---- write y = clip(z - tau)^2 * inv ----
    #pragma unroll
    for (int i = 0; i < RV4; i++) {
        float4 o;
        float d;
        d = fmaxf(v[i].x - tau, 0.0f); o.x = d * d * inv;
        d = fmaxf(v[i].y - tau, 0.0f); o.y = d * d * inv;
        d = fmaxf(v[i].z - tau, 0.0f); o.z = d * d * inv;
        d = fmaxf(v[i].w - tau, 0.0f); o.w = d * d * inv;
        orow[i * NT + tid] = o;
    }
    #pragma unroll
    for (int j = 0; j < SJ; j++) {
        const int idx = R4MAX + j * NT + tid;
        if (idx < N4) {
            float4 a = sdat[idx - R4MAX];
            float4 o;
            float d;
            d = fmaxf(0.5f * (a.x - maxv) - tau, 0.0f); o.x = d * d * inv;
            d = fmaxf(0.5f * (a.y - maxv) - tau, 0.0f); o.y = d * d * inv;
            d = fmaxf(0.5f * (a.z - maxv) - tau, 0.0f); o.z = d * d * inv;
            d = fmaxf(0.5f * (a.w - maxv) - tau, 0.0f); o.w = d * d * inv;
            orow[idx] = o;
        }
    }
}

extern "C" void kernel_launch(void* const* d_in, const int* in_sizes, int n_in,
                              void* d_out, int out_size) {
    const float* x = (const float*)d_in[0];
    float* out = (float*)d_out;
    const int rows = in_sizes[0] / N_COLS;   // 4096
    cudaFuncSetAttribute(entmax_kernel,
                         cudaFuncAttributeMaxDynamicSharedMemorySize, SMEM_BYTES);
    entmax_kernel<<<rows, NT, SMEM_BYTES>>>(x, out);
}